// round 16
// baseline (speedup 1.0000x reference)
#include <cuda_runtime.h>
#include <stdint.h>

#define MDIM  41
#define HALF  20
#define NPAIR 1261                 // (m,n) pairs with |m+n| <= 20
#define NTRIP (NPAIR * MDIM)       // 51701 triplets
#define BATCH 128
#define TPB   256
#define TPT   8                    // t per thread
#define TBLK  (TPB * TPT)          // 2048 t per block
#define MAXP  56                   // pairs spanned by a 2048-t window (<=52)
#define NCPLX (26470912LL)         // 128*2*2*51701 (real-parts buffer, floats)
#define NFLT  (52941824LL)         // full interleaved-complex float count

__device__ __forceinline__ int pair_base(int i) {
    return (i <= HALF) ? (i * (i + 41)) >> 1
                       : 651 + (((102 - i) * (i - 21)) >> 1);
}

__device__ __forceinline__ void decode_pair(int p, int& im, int& in_, int& imn) {
    int i;
    if (p < 651) {
        i = (int)((-41.0f + __fsqrt_rn(1681.0f + 8.0f * (float)p)) * 0.5f);
    } else {
        float q = (float)(p - 651);
        i = 21 + (int)((81.0f - __fsqrt_rn(6561.0f - 8.0f * q)) * 0.5f);
    }
    if (i < 0) i = 0;
    if (i > 40) i = 40;
    while (i < 40 && pair_base(i + 1) <= p) i++;
    while (i > 0 && pair_base(i) > p) i--;
    int m   = i - HALF;
    int off = p - pair_base(i);
    int nlo = (m > 0) ? -HALF : -HALF - m;
    int n   = nlo + off;
    im  = i;
    in_ = n + HALF;
    imn = m + n + HALF;
}

__device__ __forceinline__ float4 make_e1(const float4* sE, int p) {
    int im, in_, imn;
    decode_pair(p, im, in_, imn);
    float4 a = sE[im], c = sE[in_], d = sE[imn];
    float abx0 = a.x*c.x - a.y*c.y;
    float aby0 = a.x*c.y + a.y*c.x;
    float abx1 = a.z*c.z - a.w*c.w;
    float aby1 = a.z*c.w + a.w*c.z;
    return make_float4(abx0*d.x + aby0*d.y,   // e1x0
                       aby0*d.x - abx0*d.y,   // e1y0
                       abx1*d.z + aby1*d.w,   // e1x1
                       aby1*d.z - abx1*d.w);  // e1y1
}

// ---------------- MODE 1: real-parts-only layout (primary) ----------------
// out as float2: element (b*2+nm)*NTRIP + t = {feat1.re, feat2.re}
// __launch_bounds__(TPB, 2): allow up to ~128 regs so ptxas can front-batch
// all TPT iterations' shared loads (software pipelining; MLP_p1 ~ TPT).
__global__ void __launch_bounds__(TPB, 2)
sofeat_kernel(const float* __restrict__ Er,
              const float* __restrict__ Ei,
              float2* __restrict__ out2)
{
    __shared__ float4 sE[MDIM];      // (re0, im0, re1, im1)
    __shared__ float  sT1[MDIM];
    __shared__ float2 sT2[MDIM];
    __shared__ float4 sE1[MAXP];     // (e1x0, e1y0, e1x1, e1y1)

    const int tid  = threadIdx.x;
    const int b    = blockIdx.y;
    const int t_lo = blockIdx.x * TBLK;
    const int t_hi = (t_lo + TBLK < NTRIP) ? t_lo + TBLK : NTRIP;
    const int p_lo = t_lo / MDIM;
    const int np   = (t_hi - 1) / MDIM - p_lo + 1;   // <= 52

    // phase 0a: vector-load E[b] into shared
    if (tid < MDIM) {
        const float2* er2 = reinterpret_cast<const float2*>(Er + (size_t)b * (MDIM * 2));
        const float2* ei2 = reinterpret_cast<const float2*>(Ei + (size_t)b * (MDIM * 2));
        float2 er = er2[tid];
        float2 ei = ei2[tid];
        sE[tid] = make_float4(er.x, ei.x, er.y, ei.y);
    }
    __syncthreads();

    // phase 0b: terms; phase 1: E1 per pair
    if (tid < MDIM) {
        float4 e = sE[tid];
        float4 q = sE[40 - tid];
        sT1[tid] = e.x*e.x + e.y*e.y + e.z*e.z + e.w*e.w;
        float2 t2;
        t2.x = e.x*q.x - e.y*q.y + e.z*q.z - e.w*q.w;
        t2.y = e.x*q.y + e.y*q.x + e.z*q.w + e.w*q.z;
        sT2[tid] = t2;
    }
    if (tid < np)
        sE1[tid] = make_e1(sE, p_lo + tid);
    __syncthreads();

    const size_t base0 = (size_t)(b * 2 + 0) * NTRIP;
    const size_t base1 = (size_t)(b * 2 + 1) * NTRIP;

    const int t0 = t_lo + tid;
    const unsigned pp = (unsigned)t0 / MDIM;      // one divide
    const int kk0 = t0 - (int)pp * MDIM;
    const int lp0 = (int)(pp - (unsigned)p_lo);

    if (t_lo + TBLK <= NTRIP) {
        // FULL block: two-pass software pipeline.
        // Pass 1: batch ALL shared loads into registers (independent addresses).
        float4 e1r[TPT];
        float  t1r[TPT];
        float2 t2r[TPT];
        #pragma unroll
        for (int jj = 0; jj < TPT; jj++) {
            int kkj = kk0 + 10 * jj;             // 256 = 6*41 + 10
            int lpj = lp0 + 6 * jj;
            if (kkj >= 2 * MDIM)      { kkj -= 2 * MDIM; lpj += 2; }
            else if (kkj >= MDIM)     { kkj -= MDIM;     lpj += 1; }
            e1r[jj] = sE1[lpj];
            t1r[jj] = sT1[kkj];
            t2r[jj] = sT2[kkj];
        }
        // Pass 2: compute + store (stores independent, fire-and-forget)
        #pragma unroll
        for (int jj = 0; jj < TPT; jj++) {
            const float4 e1 = e1r[jj];
            const float  t1 = t1r[jj];
            const float2 t2 = t2r[jj];
            const int t = t0 + jj * TPB;
            out2[base0 + t] = make_float2(e1.x * t1, e1.x*t2.x + e1.y*t2.y);
            out2[base1 + t] = make_float2(e1.z * t1, e1.z*t2.x + e1.w*t2.y);
        }
    } else {
        // TAIL block (one per batch): guarded
        #pragma unroll
        for (int jj = 0; jj < TPT; jj++) {
            const int t = t0 + jj * TPB;
            if (t >= NTRIP) break;
            int kkj = kk0 + 10 * jj;
            int lpj = lp0 + 6 * jj;
            if (kkj >= 2 * MDIM)      { kkj -= 2 * MDIM; lpj += 2; }
            else if (kkj >= MDIM)     { kkj -= MDIM;     lpj += 1; }

            const float4 e1 = sE1[lpj];
            const float  t1 = sT1[kkj];
            const float2 t2 = sT2[kkj];
            out2[base0 + t] = make_float2(e1.x * t1, e1.x*t2.x + e1.y*t2.y);
            out2[base1 + t] = make_float2(e1.z * t1, e1.z*t2.x + e1.w*t2.y);
        }
    }
}

// ---------------- MODE 0 fallback: interleaved complex ----------------
#define FTPT  4
#define FTBLK (TPB * FTPT)
#define FMAXP 28
__global__ void __launch_bounds__(TPB)
sofeat_full_kernel(const float* __restrict__ Er,
                   const float* __restrict__ Ei,
                   float* __restrict__ out,
                   size_t cap_f)
{
    __shared__ float4 sE[MDIM];
    __shared__ float  sT1[MDIM];
    __shared__ float2 sT2[MDIM];
    __shared__ float4 sE1[FMAXP];

    const int tid  = threadIdx.x;
    const int b    = blockIdx.y;
    const int t_lo = blockIdx.x * FTBLK;
    const int t_hi = (t_lo + FTBLK < NTRIP) ? t_lo + FTBLK : NTRIP;
    const int p_lo = t_lo / MDIM;
    const int np   = (t_hi - 1) / MDIM - p_lo + 1;

    if (tid < MDIM) {
        const float2* er2 = reinterpret_cast<const float2*>(Er + (size_t)b * (MDIM * 2));
        const float2* ei2 = reinterpret_cast<const float2*>(Ei + (size_t)b * (MDIM * 2));
        float2 er = er2[tid];
        float2 ei = ei2[tid];
        sE[tid] = make_float4(er.x, ei.x, er.y, ei.y);
    }
    __syncthreads();
    if (tid < MDIM) {
        float4 e = sE[tid];
        float4 q = sE[40 - tid];
        sT1[tid] = e.x*e.x + e.y*e.y + e.z*e.z + e.w*e.w;
        float2 t2;
        t2.x = e.x*q.x - e.y*q.y + e.z*q.z - e.w*q.w;
        t2.y = e.x*q.y + e.y*q.x + e.z*q.w + e.w*q.z;
        sT2[tid] = t2;
    }
    if (tid < np)
        sE1[tid] = make_e1(sE, p_lo + tid);
    __syncthreads();

    int t = t_lo + tid;
    #pragma unroll
    for (int jj = 0; jj < FTPT; jj++, t += TPB) {
        if (t >= t_hi) break;
        const unsigned p  = (unsigned)t / MDIM;
        const int      kk = t - (int)p * MDIM;
        const float4 e1 = sE1[p - (unsigned)p_lo];
        const float  t1 = sT1[kk];
        const float2 t2 = sT2[kk];
        float4 v0 = make_float4(e1.x * t1, e1.y * t1,
                                e1.x*t2.x + e1.y*t2.y, e1.x*t2.y - e1.y*t2.x);
        float4 v1 = make_float4(e1.z * t1, e1.w * t1,
                                e1.z*t2.x + e1.w*t2.y, e1.z*t2.y - e1.w*t2.x);
        size_t f0 = (size_t)(b * 2 + 0) * (4 * (size_t)NTRIP) + 4 * (size_t)t;
        size_t f1 = (size_t)(b * 2 + 1) * (4 * (size_t)NTRIP) + 4 * (size_t)t;
        if (f0 + 4 <= cap_f) {
            *reinterpret_cast<float2*>(out + f0)     = make_float2(v0.x, v0.y);
            *reinterpret_cast<float2*>(out + f0 + 2) = make_float2(v0.z, v0.w);
        }
        if (f1 + 4 <= cap_f) {
            *reinterpret_cast<float2*>(out + f1)     = make_float2(v1.x, v1.y);
            *reinterpret_cast<float2*>(out + f1 + 2) = make_float2(v1.z, v1.w);
        }
    }
}

extern "C" void kernel_launch(void* const* d_in, const int* in_sizes, int n_in,
                              void* d_out, int out_size)
{
    if (!d_in || !d_out || n_in < 2) return;
    const float* Er = (const float*)d_in[0];
    const float* Ei = (const float*)d_in[1];
    if (!Er || !Ei) return;
    (void)in_sizes;

    const long long os = (long long)out_size;

    if (os == NCPLX || os == NCPLX * 4) {
        dim3 grid((NTRIP + TBLK - 1) / TBLK, BATCH);   // 26 x 128
        sofeat_kernel<<<grid, TPB>>>(Er, Ei, (float2*)d_out);
    } else if (os == NFLT || os == NFLT * 4) {
        dim3 grid((NTRIP + FTBLK - 1) / FTBLK, BATCH);
        sofeat_full_kernel<<<grid, TPB>>>(Er, Ei, (float*)d_out, (size_t)NFLT);
    } else {
        size_t cap = (os > 0) ? (size_t)os : 0;
        if (cap > (size_t)NFLT) cap = (size_t)NFLT;
        dim3 grid((NTRIP + FTBLK - 1) / FTBLK, BATCH);
        sofeat_full_kernel<<<grid, TPB>>>(Er, Ei, (float*)d_out, cap);
    }
}

// round 17
// speedup vs baseline: 1.1099x; 1.1099x over previous
#include <cuda_runtime.h>
#include <stdint.h>

#define MDIM  41
#define HALF  20
#define NPAIR 1261                 // (m,n) pairs with |m+n| <= 20
#define NTRIP (NPAIR * MDIM)       // 51701 triplets
#define BATCH 128
#define TPB   256
#define TPT   8                    // t per thread
#define TBLK  (TPB * TPT)          // 2048 t per block
#define MAXP  56                   // pairs spanned by a 2048-t window (<=52)
#define NCPLX (26470912LL)         // 128*2*2*51701 (real-parts buffer, floats)
#define NFLT  (52941824LL)         // full interleaved-complex float count

__device__ __forceinline__ int pair_base(int i) {
    return (i <= HALF) ? (i * (i + 41)) >> 1
                       : 651 + (((102 - i) * (i - 21)) >> 1);
}

__device__ __forceinline__ void decode_pair(int p, int& im, int& in_, int& imn) {
    int i;
    if (p < 651) {
        i = (int)((-41.0f + __fsqrt_rn(1681.0f + 8.0f * (float)p)) * 0.5f);
    } else {
        float q = (float)(p - 651);
        i = 21 + (int)((81.0f - __fsqrt_rn(6561.0f - 8.0f * q)) * 0.5f);
    }
    if (i < 0) i = 0;
    if (i > 40) i = 40;
    while (i < 40 && pair_base(i + 1) <= p) i++;
    while (i > 0 && pair_base(i) > p) i--;
    int m   = i - HALF;
    int off = p - pair_base(i);
    int nlo = (m > 0) ? -HALF : -HALF - m;
    int n   = nlo + off;
    im  = i;
    in_ = n + HALF;
    imn = m + n + HALF;
}

__device__ __forceinline__ float4 make_e1(const float4* sE, int p) {
    int im, in_, imn;
    decode_pair(p, im, in_, imn);
    float4 a = sE[im], c = sE[in_], d = sE[imn];
    float abx0 = a.x*c.x - a.y*c.y;
    float aby0 = a.x*c.y + a.y*c.x;
    float abx1 = a.z*c.z - a.w*c.w;
    float aby1 = a.z*c.w + a.w*c.z;
    return make_float4(abx0*d.x + aby0*d.y,   // e1x0
                       aby0*d.x - abx0*d.y,   // e1y0
                       abx1*d.z + aby1*d.w,   // e1x1
                       aby1*d.z - abx1*d.w);  // e1y1
}

// ---------------- MODE 1: real-parts-only layout (primary) ----------------
// out as float2: element (b*2+nm)*NTRIP + t = {feat1.re, feat2.re}
__global__ void __launch_bounds__(TPB)
sofeat_kernel(const float* __restrict__ Er,
              const float* __restrict__ Ei,
              float2* __restrict__ out2)
{
    __shared__ float4 sE[MDIM];      // (re0, im0, re1, im1)
    __shared__ float  sT1[MDIM];
    __shared__ float2 sT2[MDIM];
    __shared__ float4 sE1[MAXP];     // (e1x0, e1y0, e1x1, e1y1)

    const int tid  = threadIdx.x;
    const int b    = blockIdx.y;
    const int t_lo = blockIdx.x * TBLK;
    const int t_hi = (t_lo + TBLK < NTRIP) ? t_lo + TBLK : NTRIP;
    const int p_lo = t_lo / MDIM;
    const int np   = (t_hi - 1) / MDIM - p_lo + 1;   // <= 52

    // phase 0a: vector-load E[b] into shared
    if (tid < MDIM) {
        const float2* er2 = reinterpret_cast<const float2*>(Er + (size_t)b * (MDIM * 2));
        const float2* ei2 = reinterpret_cast<const float2*>(Ei + (size_t)b * (MDIM * 2));
        float2 er = er2[tid];
        float2 ei = ei2[tid];
        sE[tid] = make_float4(er.x, ei.x, er.y, ei.y);
    }
    __syncthreads();

    // phase 0b: terms; phase 1: E1 per pair
    if (tid < MDIM) {
        float4 e = sE[tid];
        float4 q = sE[40 - tid];
        sT1[tid] = e.x*e.x + e.y*e.y + e.z*e.z + e.w*e.w;
        float2 t2;
        t2.x = e.x*q.x - e.y*q.y + e.z*q.z - e.w*q.w;
        t2.y = e.x*q.y + e.y*q.x + e.z*q.w + e.w*q.z;
        sT2[tid] = t2;
    }
    if (tid < np)
        sE1[tid] = make_e1(sE, p_lo + tid);
    __syncthreads();

    const size_t base0 = (size_t)(b * 2 + 0) * NTRIP;
    const size_t base1 = (size_t)(b * 2 + 1) * NTRIP;

    const int t0 = t_lo + tid;
    const unsigned pp = (unsigned)t0 / MDIM;      // one divide
    const int kk0 = t0 - (int)pp * MDIM;
    const int lp0 = (int)(pp - (unsigned)p_lo);

    if (t_lo + TBLK <= NTRIP) {
        // FULL block: guard-free, independent per-iteration addressing
        #pragma unroll
        for (int jj = 0; jj < TPT; jj++) {
            int kkj = kk0 + 10 * jj;             // 256 = 6*41 + 10
            int lpj = lp0 + 6 * jj;
            if (kkj >= 2 * MDIM)      { kkj -= 2 * MDIM; lpj += 2; }
            else if (kkj >= MDIM)     { kkj -= MDIM;     lpj += 1; }

            const float4 e1 = sE1[lpj];
            const float  t1 = sT1[kkj];
            const float2 t2 = sT2[kkj];

            const int t = t0 + jj * TPB;
            out2[base0 + t] = make_float2(e1.x * t1, e1.x*t2.x + e1.y*t2.y);
            out2[base1 + t] = make_float2(e1.z * t1, e1.z*t2.x + e1.w*t2.y);
        }
    } else {
        // TAIL block (one per batch): guarded
        #pragma unroll
        for (int jj = 0; jj < TPT; jj++) {
            const int t = t0 + jj * TPB;
            if (t >= NTRIP) break;
            int kkj = kk0 + 10 * jj;
            int lpj = lp0 + 6 * jj;
            if (kkj >= 2 * MDIM)      { kkj -= 2 * MDIM; lpj += 2; }
            else if (kkj >= MDIM)     { kkj -= MDIM;     lpj += 1; }

            const float4 e1 = sE1[lpj];
            const float  t1 = sT1[kkj];
            const float2 t2 = sT2[kkj];
            out2[base0 + t] = make_float2(e1.x * t1, e1.x*t2.x + e1.y*t2.y);
            out2[base1 + t] = make_float2(e1.z * t1, e1.z*t2.x + e1.w*t2.y);
        }
    }
}

// ---------------- MODE 0 fallback: interleaved complex ----------------
#define FTPT  4
#define FTBLK (TPB * FTPT)
#define FMAXP 28
__global__ void __launch_bounds__(TPB)
sofeat_full_kernel(const float* __restrict__ Er,
                   const float* __restrict__ Ei,
                   float* __restrict__ out,
                   size_t cap_f)
{
    __shared__ float4 sE[MDIM];
    __shared__ float  sT1[MDIM];
    __shared__ float2 sT2[MDIM];
    __shared__ float4 sE1[FMAXP];

    const int tid  = threadIdx.x;
    const int b    = blockIdx.y;
    const int t_lo = blockIdx.x * FTBLK;
    const int t_hi = (t_lo + FTBLK < NTRIP) ? t_lo + FTBLK : NTRIP;
    const int p_lo = t_lo / MDIM;
    const int np   = (t_hi - 1) / MDIM - p_lo + 1;

    if (tid < MDIM) {
        const float2* er2 = reinterpret_cast<const float2*>(Er + (size_t)b * (MDIM * 2));
        const float2* ei2 = reinterpret_cast<const float2*>(Ei + (size_t)b * (MDIM * 2));
        float2 er = er2[tid];
        float2 ei = ei2[tid];
        sE[tid] = make_float4(er.x, ei.x, er.y, ei.y);
    }
    __syncthreads();
    if (tid < MDIM) {
        float4 e = sE[tid];
        float4 q = sE[40 - tid];
        sT1[tid] = e.x*e.x + e.y*e.y + e.z*e.z + e.w*e.w;
        float2 t2;
        t2.x = e.x*q.x - e.y*q.y + e.z*q.z - e.w*q.w;
        t2.y = e.x*q.y + e.y*q.x + e.z*q.w + e.w*q.z;
        sT2[tid] = t2;
    }
    if (tid < np)
        sE1[tid] = make_e1(sE, p_lo + tid);
    __syncthreads();

    int t = t_lo + tid;
    #pragma unroll
    for (int jj = 0; jj < FTPT; jj++, t += TPB) {
        if (t >= t_hi) break;
        const unsigned p  = (unsigned)t / MDIM;
        const int      kk = t - (int)p * MDIM;
        const float4 e1 = sE1[p - (unsigned)p_lo];
        const float  t1 = sT1[kk];
        const float2 t2 = sT2[kk];
        float4 v0 = make_float4(e1.x * t1, e1.y * t1,
                                e1.x*t2.x + e1.y*t2.y, e1.x*t2.y - e1.y*t2.x);
        float4 v1 = make_float4(e1.z * t1, e1.w * t1,
                                e1.z*t2.x + e1.w*t2.y, e1.z*t2.y - e1.w*t2.x);
        size_t f0 = (size_t)(b * 2 + 0) * (4 * (size_t)NTRIP) + 4 * (size_t)t;
        size_t f1 = (size_t)(b * 2 + 1) * (4 * (size_t)NTRIP) + 4 * (size_t)t;
        if (f0 + 4 <= cap_f) {
            *reinterpret_cast<float2*>(out + f0)     = make_float2(v0.x, v0.y);
            *reinterpret_cast<float2*>(out + f0 + 2) = make_float2(v0.z, v0.w);
        }
        if (f1 + 4 <= cap_f) {
            *reinterpret_cast<float2*>(out + f1)     = make_float2(v1.x, v1.y);
            *reinterpret_cast<float2*>(out + f1 + 2) = make_float2(v1.z, v1.w);
        }
    }
}

extern "C" void kernel_launch(void* const* d_in, const int* in_sizes, int n_in,
                              void* d_out, int out_size)
{
    if (!d_in || !d_out || n_in < 2) return;
    const float* Er = (const float*)d_in[0];
    const float* Ei = (const float*)d_in[1];
    if (!Er || !Ei) return;
    (void)in_sizes;

    const long long os = (long long)out_size;

    if (os == NCPLX || os == NCPLX * 4) {
        dim3 grid((NTRIP + TBLK - 1) / TBLK, BATCH);   // 26 x 128
        sofeat_kernel<<<grid, TPB>>>(Er, Ei, (float2*)d_out);
    } else if (os == NFLT || os == NFLT * 4) {
        dim3 grid((NTRIP + FTBLK - 1) / FTBLK, BATCH);
        sofeat_full_kernel<<<grid, TPB>>>(Er, Ei, (float*)d_out, (size_t)NFLT);
    } else {
        size_t cap = (os > 0) ? (size_t)os : 0;
        if (cap > (size_t)NFLT) cap = (size_t)NFLT;
        dim3 grid((NTRIP + FTBLK - 1) / FTBLK, BATCH);
        sofeat_full_kernel<<<grid, TPB>>>(Er, Ei, (float*)d_out, cap);
    }
}